// round 2
// baseline (speedup 1.0000x reference)
#include <cuda_runtime.h>
#include <cstdint>

#define NB      32768
#define IN_DIM  2048
#define OUT_DIM 2432

#define C_INV3 0.57735026918962576451f
#define C_INV5 0.44721359549995793928f
#define C_INV7 0.37796447300922722721f

// Scratch for mode-1 mixed factors: [NB][384], already scaled by 1/sqrt(d).
__device__ float g_mixed[(size_t)NB * 384];

// ---------------------------------------------------------------------------
// Kernel 1: mode-1 matvec bank.
// g_mixed[b, p*128+u] = (1/sqrt(d_p)) * sum_v x2[b,v] * weight[(4+p)*16384 + u*128 + v]
// W' stored transposed+scaled in smem with pad 385 (conflict-free both ways).
// ---------------------------------------------------------------------------
__global__ void __launch_bounds__(256, 1)
mode1_gemm_kernel(const float* __restrict__ x2, const float* __restrict__ weight)
{
    extern __shared__ float smem[];
    float* WT   = smem;               // [128][385] : WT[v*385 + u'], u' in [0,384)
    float* xrow = smem + 128 * 385;   // [8 warps][4 rows][128]

    const int tid  = threadIdx.x;
    const int lane = tid & 31;
    const int warp = tid >> 5;

    // Load + transpose + scale the three mode-1 weight matrices.
    for (int g = tid; g < 3 * 16384; g += 256) {
        int p   = g >> 14;
        int rem = g & 16383;
        int u   = rem >> 7;
        int v   = rem & 127;
        float sc = (p == 0) ? C_INV3 : ((p == 1) ? C_INV5 : C_INV7);
        WT[v * 385 + (p << 7) + u] = weight[4 * 16384 + g] * sc;
    }
    __syncthreads();

    float* myrow = xrow + warp * 512;
    const int step = gridDim.x * 8 * 4;
    for (int r0 = (blockIdx.x * 8 + warp) * 4; r0 < NB; r0 += step) {
        // Stage 4 rows of x2[:,0:128] (coalesced float4).
        #pragma unroll
        for (int r = 0; r < 4; r++) {
            const float4* src = (const float4*)(x2 + (size_t)(r0 + r) * IN_DIM);
            ((float4*)(myrow + r * 128))[lane] = src[lane];
        }
        __syncwarp();

        float acc[4][12];
        #pragma unroll
        for (int r = 0; r < 4; r++)
            #pragma unroll
            for (int i = 0; i < 12; i++) acc[r][i] = 0.0f;

        #pragma unroll 4
        for (int v = 0; v < 128; v++) {
            float wv[12];
            #pragma unroll
            for (int i = 0; i < 12; i++) wv[i] = WT[v * 385 + lane + 32 * i];
            #pragma unroll
            for (int r = 0; r < 4; r++) {
                float s = myrow[r * 128 + v];   // warp-uniform broadcast
                #pragma unroll
                for (int i = 0; i < 12; i++) acc[r][i] = fmaf(s, wv[i], acc[r][i]);
            }
        }

        #pragma unroll
        for (int r = 0; r < 4; r++) {
            float* dst = g_mixed + (size_t)(r0 + r) * 384;
            #pragma unroll
            for (int i = 0; i < 12; i++) dst[lane + 32 * i] = acc[r][i];
        }
        __syncwarp();
    }
}

// ---------------------------------------------------------------------------
// Group kernel: one depth-d mode-0 path, optionally fused with its mode-1
// epilogue (same x1 slice). Persistent CTAs, 8 warps, ROWS rows per warp pass.
//   tmp[u,k] = sum_v W[u,v] * x2[b, in2s + v*D + k]
//   out[b, outs0+u]     = (sum_k x1s[u*D+k]*tmp[u,k]) * inv_d * mask
//   out[b, outs1+u*D+k] = x1s[u*D+k] * g_mixed[b, moff + u] * mask   (HAS_M1)
// ---------------------------------------------------------------------------
template<int D, int ROWS, bool HAS_M1>
__global__ void __launch_bounds__(256, 1)
group_kernel(const float* __restrict__ x1, const float* __restrict__ x2,
             const float* __restrict__ weight, const float* __restrict__ mask,
             float* __restrict__ out,
             int in1s, int in2s, int outs0, int outs1, int ws0, int moff,
             float inv_d)
{
    extern __shared__ float smem[];
    float* WT = smem;                                  // [128][129]
    const int tid  = threadIdx.x;
    const int lane = tid & 31;
    const int warp = tid >> 5;

    const int RB = ROWS * 2 * D * 128;                 // floats per warp
    float* x1s = smem + 128 * 129 + warp * RB;         // [ROWS][D*128]
    float* x2s = x1s + ROWS * D * 128;                 // [ROWS][D*128]

    // Load mode-0 weight transposed, pad 129 (conflict-free store & read).
    for (int g = tid; g < 16384; g += 256) {
        int u = g >> 7, v = g & 127;
        WT[v * 129 + u] = weight[ws0 + g];
    }
    __syncthreads();

    const int step = gridDim.x * 8 * ROWS;
    for (int r0 = (blockIdx.x * 8 + warp) * ROWS; r0 < NB; r0 += step) {
        // Stage ROWS rows of x1/x2 slices (coalesced float4).
        #pragma unroll
        for (int r = 0; r < ROWS; r++) {
            const float4* s1 = (const float4*)(x1 + (size_t)(r0 + r) * IN_DIM + in1s);
            const float4* s2 = (const float4*)(x2 + (size_t)(r0 + r) * IN_DIM + in2s);
            float4* d1 = (float4*)(x1s + r * D * 128);
            float4* d2 = (float4*)(x2s + r * D * 128);
            #pragma unroll
            for (int j = 0; j < D; j++) {
                d1[j * 32 + lane] = s1[j * 32 + lane];
                d2[j * 32 + lane] = s2[j * 32 + lane];
            }
        }
        __syncwarp();

        // Matvec bank: acc[r][i][k] = tmp for u = lane + 32*i.
        float acc[ROWS][4][D];
        #pragma unroll
        for (int r = 0; r < ROWS; r++)
            #pragma unroll
            for (int i = 0; i < 4; i++)
                #pragma unroll
                for (int k = 0; k < D; k++) acc[r][i][k] = 0.0f;

        #pragma unroll 2
        for (int v = 0; v < 128; v++) {
            float wv[4];
            #pragma unroll
            for (int i = 0; i < 4; i++) wv[i] = WT[v * 129 + lane + 32 * i];
            #pragma unroll
            for (int r = 0; r < ROWS; r++) {
                #pragma unroll
                for (int k = 0; k < D; k++) {
                    float s = x2s[r * D * 128 + v * D + k];  // broadcast
                    #pragma unroll
                    for (int i = 0; i < 4; i++)
                        acc[r][i][k] = fmaf(wv[i], s, acc[r][i][k]);
                }
            }
        }

        // Mode-0 reduce with x1, masked store (u = lane+32i -> coalesced).
        #pragma unroll
        for (int r = 0; r < ROWS; r++) {
            float* orow = out + (size_t)(r0 + r) * OUT_DIM;
            #pragma unroll
            for (int i = 0; i < 4; i++) {
                int u = lane + 32 * i;
                float m = 0.0f;
                #pragma unroll
                for (int k = 0; k < D; k++)
                    m = fmaf(x1s[r * D * 128 + u * D + k], acc[r][i][k], m);
                int col = outs0 + u;
                orow[col] = m * inv_d * mask[col];
            }
        }

        // Mode-1 epilogue (reuses staged x1 slice; vectorized stores).
        if constexpr (HAS_M1) {
            #pragma unroll
            for (int r = 0; r < ROWS; r++) {
                const float* mrow = g_mixed + (size_t)(r0 + r) * 384 + moff; // pre-scaled
                float4* o4        = (float4*)(out + (size_t)(r0 + r) * OUT_DIM + outs1);
                const float4* x14 = (const float4*)(x1s + r * D * 128);
                const float4* mk4 = (const float4*)(mask + outs1);
                #pragma unroll
                for (int jj = 0; jj < D; jj++) {
                    int j = jj * 32 + lane;
                    float4 xv  = x14[j];
                    float4 mkv = mk4[j];
                    int e = 4 * j;
                    float4 o;
                    o.x = xv.x * mrow[(e    ) / D] * mkv.x;
                    o.y = xv.y * mrow[(e + 1) / D] * mkv.y;
                    o.z = xv.z * mrow[(e + 2) / D] * mkv.z;
                    o.w = xv.w * mrow[(e + 3) / D] * mkv.w;
                    o4[j] = o;
                }
            }
        }
        __syncwarp();
    }
}

// ---------------------------------------------------------------------------
extern "C" void kernel_launch(void* const* d_in, const int* in_sizes, int n_in,
                              void* d_out, int out_size)
{
    (void)in_sizes; (void)n_in; (void)out_size;
    const float* x1   = (const float*)d_in[0];
    const float* x2   = (const float*)d_in[1];
    const float* w    = (const float*)d_in[2];
    const float* mask = (const float*)d_in[3];
    float* out        = (float*)d_out;

    const int SM_M1 = 128 * 385 * 4 + 8 * 4 * 128 * 4;                 // 213504
    const int SM_G1 = 128 * 129 * 4 + 8 * 8 * 2 * 1 * 128 * 4;         // 131584
    const int SM_G3 = 128 * 129 * 4 + 8 * 4 * 2 * 3 * 128 * 4;         // 164352
    const int SM_G5 = 128 * 129 * 4 + 8 * 2 * 2 * 5 * 128 * 4;         // 147968
    const int SM_G7 = 128 * 129 * 4 + 8 * 2 * 2 * 7 * 128 * 4;         // 180736

    cudaFuncSetAttribute(mode1_gemm_kernel,
                         cudaFuncAttributeMaxDynamicSharedMemorySize, SM_M1);
    cudaFuncSetAttribute(group_kernel<1, 8, false>,
                         cudaFuncAttributeMaxDynamicSharedMemorySize, SM_G1);
    cudaFuncSetAttribute(group_kernel<3, 4, true>,
                         cudaFuncAttributeMaxDynamicSharedMemorySize, SM_G3);
    cudaFuncSetAttribute(group_kernel<5, 2, true>,
                         cudaFuncAttributeMaxDynamicSharedMemorySize, SM_G5);
    cudaFuncSetAttribute(group_kernel<7, 2, true>,
                         cudaFuncAttributeMaxDynamicSharedMemorySize, SM_G7);

    const int GRID = 148;   // persistent, 1 CTA/SM (smem-bound anyway)

    // mode-1 GEMM first: groups 3/5/7 consume g_mixed (same-stream ordering).
    mode1_gemm_kernel<<<GRID, 256, SM_M1>>>(x2, w);

    // path layout: (in1s, in2s, outs0, outs1, ws0, moff, 1/sqrt(d))
    group_kernel<1, 8, false><<<GRID, 256, SM_G1>>>(
        x1, x2, w, mask, out, 0, 0, 0, 0, 0 * 16384, 0, 1.0f);
    group_kernel<3, 4, true><<<GRID, 256, SM_G3>>>(
        x1, x2, w, mask, out, 128, 128, 128, 512, 1 * 16384, 0, C_INV3);
    group_kernel<5, 2, true><<<GRID, 256, SM_G5>>>(
        x1, x2, w, mask, out, 512, 512, 256, 896, 2 * 16384, 128, C_INV5);
    group_kernel<7, 2, true><<<GRID, 256, SM_G7>>>(
        x1, x2, w, mask, out, 1152, 1152, 384, 1536, 3 * 16384, 256, C_INV7);
}

// round 4
// speedup vs baseline: 1.2820x; 1.2820x over previous
#include <cuda_runtime.h>
#include <cstdint>

typedef unsigned long long ull;

#define NB      32768
#define IN_DIM  2048
#define OUT_DIM 2432

#define C_INV3 0.57735026918962576451f
#define C_INV5 0.44721359549995793928f
#define C_INV7 0.37796447300922722721f

// Scratch for mode-1 mixed factors: [NB][384], pre-scaled by 1/sqrt(d).
__device__ float g_mixed[(size_t)NB * 384];

// ---------------- f32x2 packed-FMA helpers (sm_103a FFMA2) ----------------
__device__ __forceinline__ ull f2dup(float s) {
    ull d; asm("mov.b64 %0, {%1, %1};" : "=l"(d) : "f"(s)); return d;
}
__device__ __forceinline__ ull f2pack(float lo, float hi) {
    ull d; asm("mov.b64 %0, {%1, %2};" : "=l"(d) : "f"(lo), "f"(hi)); return d;
}
__device__ __forceinline__ void fma2(ull& acc, ull a, ull b) {
    asm("fma.rn.f32x2 %0, %1, %2, %0;" : "+l"(acc) : "l"(a), "l"(b));
}
__device__ __forceinline__ float2 f2unpack(ull v) {
    float2 r; asm("mov.b64 {%0, %1}, %2;" : "=f"(r.x), "=f"(r.y) : "l"(v)); return r;
}

// ---------------------------------------------------------------------------
// Mode-1 kernel: g_mixed[b, p*128+u] = (1/sqrt(d_p)) * sum_v x2[b,v]*W'[p][u,v]
// W' (3x128x128) kept transposed in smem as [v][u'-quad] float4 (192KB, 1 CTA).
// f32x2 over u-pairs: w-pairs are adjacent float4 components (free packs).
// ---------------------------------------------------------------------------
__global__ void __launch_bounds__(256, 1)
mode1_kernel(const float* __restrict__ x2, const float* __restrict__ weight)
{
    extern __shared__ float smem[];
    // smem[0 .. 128*384) : WT, word layout: ((v*96 + quad)*4 + comp), quad=u'/4
    float* x2s = smem + 128 * 384;                 // [8 warps][4 rows][128]
    constexpr int R = 4;                           // divides NB (power of 2)

    const int tid  = threadIdx.x;
    const int lane = tid & 31;
    const int warp = tid >> 5;

    // Load W' transposed + scaled. Coalesced float4 LDG; scattered STS (once).
    for (int f = tid; f < 3 * 128 * 32; f += 256) {
        int p   = f / 4096;
        int rem = f - p * 4096;
        int u   = rem >> 5;          // row within this p-block
        int vb  = rem & 31;          // v-quad
        float sc = (p == 0) ? C_INV3 : ((p == 1) ? C_INV5 : C_INV7);
        float4 w4 = ((const float4*)(weight + (size_t)(4 + p) * 16384))[rem];
        int q = p * 32 + (u >> 2), uc = u & 3;
        smem[((4 * vb + 0) * 96 + q) * 4 + uc] = w4.x * sc;
        smem[((4 * vb + 1) * 96 + q) * 4 + uc] = w4.y * sc;
        smem[((4 * vb + 2) * 96 + q) * 4 + uc] = w4.z * sc;
        smem[((4 * vb + 3) * 96 + q) * 4 + uc] = w4.w * sc;
    }
    __syncthreads();

    const float4* WT4 = (const float4*)smem;
    float* myrows = x2s + warp * (R * 128);

    const int step = gridDim.x * 8 * R;
    for (int r0 = (blockIdx.x * 8 + warp) * R; r0 < NB; r0 += step) {
        #pragma unroll
        for (int r = 0; r < R; r++) {
            const float4* src = (const float4*)(x2 + (size_t)(r0 + r) * IN_DIM);
            ((float4*)(myrows + r * 128))[lane] = src[lane];
        }
        __syncwarp();

        ull acc[R][6];
        #pragma unroll
        for (int r = 0; r < R; r++)
            #pragma unroll
            for (int t = 0; t < 6; t++) acc[r][t] = 0ULL;

        #pragma unroll 4
        for (int v = 0; v < 128; v++) {
            float4 wa = WT4[v * 96 + lane];
            float4 wb = WT4[v * 96 + lane + 32];
            float4 wc = WT4[v * 96 + lane + 64];
            ull wp[6];
            wp[0] = f2pack(wa.x, wa.y); wp[1] = f2pack(wa.z, wa.w);
            wp[2] = f2pack(wb.x, wb.y); wp[3] = f2pack(wb.z, wb.w);
            wp[4] = f2pack(wc.x, wc.y); wp[5] = f2pack(wc.z, wc.w);
            #pragma unroll
            for (int r = 0; r < R; r++) {
                ull s2 = f2dup(myrows[r * 128 + v]);   // warp-uniform broadcast
                #pragma unroll
                for (int t = 0; t < 6; t++) fma2(acc[r][t], wp[t], s2);
            }
        }

        #pragma unroll
        for (int r = 0; r < R; r++) {
            float4* dst = (float4*)(g_mixed + (size_t)(r0 + r) * 384);
            #pragma unroll
            for (int i = 0; i < 3; i++) {
                float2 a = f2unpack(acc[r][2 * i]);
                float2 b = f2unpack(acc[r][2 * i + 1]);
                float4 o; o.x = a.x; o.y = a.y; o.z = b.x; o.w = b.y;
                dst[lane + 32 * i] = o;
            }
        }
        __syncwarp();
    }
}

// ---------------------------------------------------------------------------
// Group kernel for depth D (mode-0 path + optional fused mode-1 epilogue).
// Lane owns u-quad u = 4*lane + j  (j<4): all gmem traffic float4-coalesced.
//   tmp[u,k] = sum_v W[u,v] * x2[b, in2s + v*D + k]        (f32x2 over k-pairs)
//   out[b, outs0+u]       = (sum_k x1[u*D+k]*tmp[u,k]) * inv_d * mask
//   out[b, outs1+u*D+k]   = x1[u*D+k] * g_mixed[b,moff+u] * mask    (HAS_M1)
// x2 staged in smem with even stride DP (padded, pad zeroed); x1 read straight
// from gmem into registers at the epilogue (contiguous 4D floats per lane).
// NOTE: ROWS must be a power of two (divides NB=32768) — persistent loop has
// no tail guard.
// ---------------------------------------------------------------------------
template<int D, int ROWS, bool HAS_M1>
__global__ void __launch_bounds__(256, 2)
group_kernel(const float* __restrict__ x1, const float* __restrict__ x2,
             const float* __restrict__ weight, const float* __restrict__ mask,
             float* __restrict__ out,
             int in1s, int in2s, int outs0, int outs1, int ws0, int moff,
             float inv_d)
{
    static_assert((ROWS & (ROWS - 1)) == 0, "ROWS must divide NB");
    // D==1: no k-pairs, stage at stride 1. D>1: even padded stride for ULL loads.
    constexpr int DP = (D == 1) ? 1 : ((D & 1) ? (D + 1) : D);
    constexpr int KP = (D == 1) ? 1 : (DP / 2);   // k-pairs (packed path only)
    extern __shared__ float smem[];
    // smem[0 .. 128*128): WT word layout ((v*32 + uquad)*4 + comp)
    float* x2s_all = smem + 128 * 128;

    const int tid  = threadIdx.x;
    const int lane = tid & 31;
    const int warp = tid >> 5;
    float* x2s = x2s_all + warp * (ROWS * 128 * DP);

    // Load mode-0 W transposed into quad layout (coalesced LDG, once).
    for (int f = tid; f < 128 * 32; f += 256) {
        int u = f >> 5, vb = f & 31;
        float4 w4 = ((const float4*)(weight + ws0))[f];   // W[u][4vb..4vb+3]
        int q = u >> 2, uc = u & 3;
        smem[((4 * vb + 0) * 32 + q) * 4 + uc] = w4.x;
        smem[((4 * vb + 1) * 32 + q) * 4 + uc] = w4.y;
        smem[((4 * vb + 2) * 32 + q) * 4 + uc] = w4.z;
        smem[((4 * vb + 3) * 32 + q) * 4 + uc] = w4.w;
    }
    __syncthreads();
    const float4* WT4 = (const float4*)smem;

    const int step = gridDim.x * 8 * ROWS;
    for (int r0 = (blockIdx.x * 8 + warp) * ROWS; r0 < NB; r0 += step) {
        // ---- stage x2 slices (coalesced LDG.128, scatter STS into DP pad) ----
        #pragma unroll
        for (int r = 0; r < ROWS; r++) {
            const float4* src = (const float4*)(x2 + (size_t)(r0 + r) * IN_DIM + in2s);
            float* dst = x2s + r * (128 * DP);
            if constexpr (D == 1) {
                ((float4*)dst)[lane] = src[lane];          // stride 1, 128 floats
            } else {
                #pragma unroll
                for (int j = 0; j < D; j++) {
                    float4 v4 = src[j * 32 + lane];
                    int e = 4 * (j * 32 + lane);
                    dst[((e + 0) / D) * DP + ((e + 0) % D)] = v4.x;
                    dst[((e + 1) / D) * DP + ((e + 1) % D)] = v4.y;
                    dst[((e + 2) / D) * DP + ((e + 2) % D)] = v4.z;
                    dst[((e + 3) / D) * DP + ((e + 3) % D)] = v4.w;
                }
                if constexpr (D & 1) {
                    #pragma unroll
                    for (int vv = 0; vv < 4; vv++)
                        dst[(vv * 32 + lane) * DP + D] = 0.0f;  // zero pad slot
                }
            }
        }
        __syncwarp();

        // ---- main bank: tmp[u,k] accumulation ----
        float accs[D == 1 ? ROWS : 1][4];          // scalar path (D==1)
        ull   acc2[D == 1 ? 1 : ROWS][4][KP];      // packed path (D>1)

        if constexpr (D == 1) {
            #pragma unroll
            for (int r = 0; r < ROWS; r++)
                #pragma unroll
                for (int j = 0; j < 4; j++) accs[r][j] = 0.0f;
            #pragma unroll 4
            for (int v = 0; v < 128; v++) {
                float4 wv = WT4[v * 32 + lane];
                #pragma unroll
                for (int r = 0; r < ROWS; r++) {
                    float s = x2s[r * 128 + v];
                    accs[r][0] = fmaf(wv.x, s, accs[r][0]);
                    accs[r][1] = fmaf(wv.y, s, accs[r][1]);
                    accs[r][2] = fmaf(wv.z, s, accs[r][2]);
                    accs[r][3] = fmaf(wv.w, s, accs[r][3]);
                }
            }
        } else {
            #pragma unroll
            for (int r = 0; r < ROWS; r++)
                #pragma unroll
                for (int j = 0; j < 4; j++)
                    #pragma unroll
                    for (int kp = 0; kp < KP; kp++) acc2[r][j][kp] = 0ULL;
            #pragma unroll 4
            for (int v = 0; v < 128; v++) {
                float4 wv = WT4[v * 32 + lane];
                ull w2[4];
                w2[0] = f2dup(wv.x); w2[1] = f2dup(wv.y);
                w2[2] = f2dup(wv.z); w2[3] = f2dup(wv.w);
                #pragma unroll
                for (int r = 0; r < ROWS; r++) {
                    const float* srow = x2s + r * (128 * DP) + v * DP;
                    #pragma unroll
                    for (int kp = 0; kp < KP; kp++) {
                        ull s2 = *(const ull*)(srow + 2 * kp);  // aligned (DP even)
                        #pragma unroll
                        for (int j = 0; j < 4; j++) fma2(acc2[r][j][kp], w2[j], s2);
                    }
                }
            }
        }

        // ---- epilogue per row ----
        #pragma unroll
        for (int r = 0; r < ROWS; r++) {
            const size_t b = (size_t)(r0 + r);
            // x1 slice for this lane's u-quad: contiguous 4*D floats (coalesced)
            float x1v[4 * D];
            {
                const float4* x1p =
                    (const float4*)(x1 + b * IN_DIM + in1s + 4 * lane * D);
                #pragma unroll
                for (int q = 0; q < D; q++) {
                    float4 t = x1p[q];
                    x1v[4 * q + 0] = t.x; x1v[4 * q + 1] = t.y;
                    x1v[4 * q + 2] = t.z; x1v[4 * q + 3] = t.w;
                }
            }
            // mode-0 reduce over k
            float m[4];
            #pragma unroll
            for (int j = 0; j < 4; j++) {
                float acc = 0.0f;
                if constexpr (D == 1) {
                    acc = x1v[j] * accs[r][j];
                } else {
                    #pragma unroll
                    for (int kp = 0; kp < KP; kp++) {
                        float2 a = f2unpack(acc2[r][j][kp]);
                        int k0 = 2 * kp, k1 = 2 * kp + 1;
                        acc = fmaf(x1v[j * D + k0], a.x, acc);
                        if (k1 < D) acc = fmaf(x1v[j * D + k1], a.y, acc);
                    }
                }
                m[j] = acc;
            }
            {
                float4 mk = ((const float4*)(mask + outs0))[lane];
                float4 o; o.x = m[0] * inv_d * mk.x; o.y = m[1] * inv_d * mk.y;
                o.z = m[2] * inv_d * mk.z; o.w = m[3] * inv_d * mk.w;
                ((float4*)(out + b * OUT_DIM + outs0))[lane] = o;
            }
            // fused mode-1 epilogue (same x1 slice, mixed pre-scaled)
            if constexpr (HAS_M1) {
                float4 mix4 = ((const float4*)(g_mixed + b * 384 + moff))[lane];
                float mixv[4] = {mix4.x, mix4.y, mix4.z, mix4.w};
                const float4* mkp =
                    (const float4*)(mask + outs1 + 4 * lane * D);
                float4* op = (float4*)(out + b * OUT_DIM + outs1 + 4 * lane * D);
                #pragma unroll
                for (int q = 0; q < D; q++) {
                    float4 mq = mkp[q];
                    float4 o;
                    o.x = x1v[4 * q + 0] * mixv[(4 * q + 0) / D] * mq.x;
                    o.y = x1v[4 * q + 1] * mixv[(4 * q + 1) / D] * mq.y;
                    o.z = x1v[4 * q + 2] * mixv[(4 * q + 2) / D] * mq.z;
                    o.w = x1v[4 * q + 3] * mixv[(4 * q + 3) / D] * mq.w;
                    op[q] = o;
                }
            }
        }
        __syncwarp();
    }
}

// ---------------------------------------------------------------------------
extern "C" void kernel_launch(void* const* d_in, const int* in_sizes, int n_in,
                              void* d_out, int out_size)
{
    (void)in_sizes; (void)n_in; (void)out_size;
    const float* x1   = (const float*)d_in[0];
    const float* x2   = (const float*)d_in[1];
    const float* w    = (const float*)d_in[2];
    const float* mask = (const float*)d_in[3];
    float* out        = (float*)d_out;

    // smem sizes (bytes) — group kernels sized for 2 CTAs/SM (228KB/SM).
    const int SM_M1 = (128 * 384 + 8 * 4 * 128) * 4;           // 212992 (1 CTA)
    const int SM_G1 = (128 * 128 + 8 * 8 * 128 * 1) * 4;       //  98304 (D=1,R=8,DP=1)
    const int SM_G3 = (128 * 128 + 8 * 2 * 128 * 4) * 4;       //  98304 (D=3,R=2,DP=4)
    const int SM_G5 = (128 * 128 + 8 * 2 * 128 * 6) * 4;       // 114688 (D=5,R=2,DP=6)
    const int SM_G7 = (128 * 128 + 8 * 1 * 128 * 8) * 4;       //  98304 (D=7,R=1,DP=8)

    cudaFuncSetAttribute(mode1_kernel,
                         cudaFuncAttributeMaxDynamicSharedMemorySize, SM_M1);
    cudaFuncSetAttribute(group_kernel<1, 8, false>,
                         cudaFuncAttributeMaxDynamicSharedMemorySize, SM_G1);
    cudaFuncSetAttribute(group_kernel<3, 2, true>,
                         cudaFuncAttributeMaxDynamicSharedMemorySize, SM_G3);
    cudaFuncSetAttribute(group_kernel<5, 2, true>,
                         cudaFuncAttributeMaxDynamicSharedMemorySize, SM_G5);
    cudaFuncSetAttribute(group_kernel<7, 1, true>,
                         cudaFuncAttributeMaxDynamicSharedMemorySize, SM_G7);

    const int G1 = 148;   // mode-1: 1 CTA/SM (192KB weights)
    const int G2 = 296;   // groups: 2 CTAs/SM

    // mode-1 first (groups 3/5/7 consume g_mixed; same-stream ordering).
    mode1_kernel<<<G1, 256, SM_M1>>>(x2, w);

    group_kernel<1, 8, false><<<G2, 256, SM_G1>>>(
        x1, x2, w, mask, out, 0, 0, 0, 0, 0 * 16384, 0, 1.0f);
    group_kernel<3, 2, true><<<G2, 256, SM_G3>>>(
        x1, x2, w, mask, out, 128, 128, 128, 512, 1 * 16384, 0, C_INV3);
    group_kernel<5, 2, true><<<G2, 256, SM_G5>>>(
        x1, x2, w, mask, out, 512, 512, 256, 896, 2 * 16384, 128, C_INV5);
    group_kernel<7, 1, true><<<G2, 256, SM_G7>>>(
        x1, x2, w, mask, out, 1152, 1152, 384, 1536, 3 * 16384, 256, C_INV7);
}

// round 6
// speedup vs baseline: 1.2883x; 1.0049x over previous
#include <cuda_runtime.h>
#include <cstdint>

typedef unsigned long long ull;

#define NB      32768
#define IN_DIM  2048
#define OUT_DIM 2432

#define C_INV3 0.57735026918962576451f
#define C_INV5 0.44721359549995793928f
#define C_INV7 0.37796447300922722721f

// Scratch for mode-1 mixed factors: [NB][384], pre-scaled by 1/sqrt(d).
__device__ float g_mixed[(size_t)NB * 384];

// ---------------- f32x2 packed-FMA helpers ----------------
__device__ __forceinline__ ull f2dup(float s) {
    ull d; asm("mov.b64 %0, {%1, %1};" : "=l"(d) : "f"(s)); return d;
}
__device__ __forceinline__ ull f2pack(float lo, float hi) {
    ull d; asm("mov.b64 %0, {%1, %2};" : "=l"(d) : "f"(lo), "f"(hi)); return d;
}
__device__ __forceinline__ void fma2(ull& acc, ull a, ull b) {
    asm("fma.rn.f32x2 %0, %1, %2, %0;" : "+l"(acc) : "l"(a), "l"(b));
}
__device__ __forceinline__ float2 f2unpack(ull v) {
    float2 r; asm("mov.b64 {%0, %1}, %2;" : "=f"(r.x), "=f"(r.y) : "l"(v)); return r;
}

// ---------------- tf32 mma.sync helpers (base sm_103, no 'a' needed) -------
__device__ __forceinline__ uint32_t cvt_tf32(float x) {
    uint32_t r; asm("cvt.rna.tf32.f32 %0, %1;" : "=r"(r) : "f"(x)); return r;
}
__device__ __forceinline__ void mma_tf32(float c[4], const uint32_t a[4],
                                         uint32_t b0, uint32_t b1) {
    asm volatile(
        "mma.sync.aligned.m16n8k8.row.col.f32.tf32.tf32.f32 "
        "{%0,%1,%2,%3}, {%4,%5,%6,%7}, {%8,%9}, {%0,%1,%2,%3};"
        : "+f"(c[0]), "+f"(c[1]), "+f"(c[2]), "+f"(c[3])
        : "r"(a[0]), "r"(a[1]), "r"(a[2]), "r"(a[3]), "r"(b0), "r"(b1));
}

// ---------------------------------------------------------------------------
// Mode-1 kernel (FFMA2, exact fp32):
//   g_mixed[b, p*128+u] = (1/sqrt(d_p)) * sum_v x2[b,v] * W'[p][u,v]
// ---------------------------------------------------------------------------
__global__ void __launch_bounds__(256, 1)
mode1_kernel(const float* __restrict__ x2, const float* __restrict__ weight)
{
    extern __shared__ float smem[];
    float* x2s = smem + 128 * 384;
    constexpr int R = 4;

    const int tid  = threadIdx.x;
    const int lane = tid & 31;
    const int warp = tid >> 5;

    for (int f = tid; f < 3 * 128 * 32; f += 256) {
        int p   = f / 4096;
        int rem = f - p * 4096;
        int u   = rem >> 5;
        int vb  = rem & 31;
        float sc = (p == 0) ? C_INV3 : ((p == 1) ? C_INV5 : C_INV7);
        float4 w4 = ((const float4*)(weight + (size_t)(4 + p) * 16384))[rem];
        int q = p * 32 + (u >> 2), uc = u & 3;
        smem[((4 * vb + 0) * 96 + q) * 4 + uc] = w4.x * sc;
        smem[((4 * vb + 1) * 96 + q) * 4 + uc] = w4.y * sc;
        smem[((4 * vb + 2) * 96 + q) * 4 + uc] = w4.z * sc;
        smem[((4 * vb + 3) * 96 + q) * 4 + uc] = w4.w * sc;
    }
    __syncthreads();

    const float4* WT4 = (const float4*)smem;
    float* myrows = x2s + warp * (R * 128);

    const int step = gridDim.x * 8 * R;
    for (int r0 = (blockIdx.x * 8 + warp) * R; r0 < NB; r0 += step) {
        #pragma unroll
        for (int r = 0; r < R; r++) {
            const float4* src = (const float4*)(x2 + (size_t)(r0 + r) * IN_DIM);
            ((float4*)(myrows + r * 128))[lane] = src[lane];
        }
        __syncwarp();

        ull acc[R][6];
        #pragma unroll
        for (int r = 0; r < R; r++)
            #pragma unroll
            for (int t = 0; t < 6; t++) acc[r][t] = 0ULL;

        #pragma unroll 4
        for (int v = 0; v < 128; v++) {
            float4 wa = WT4[v * 96 + lane];
            float4 wb = WT4[v * 96 + lane + 32];
            float4 wc = WT4[v * 96 + lane + 64];
            ull wp[6];
            wp[0] = f2pack(wa.x, wa.y); wp[1] = f2pack(wa.z, wa.w);
            wp[2] = f2pack(wb.x, wb.y); wp[3] = f2pack(wb.z, wb.w);
            wp[4] = f2pack(wc.x, wc.y); wp[5] = f2pack(wc.z, wc.w);
            #pragma unroll
            for (int r = 0; r < R; r++) {
                ull s2 = f2dup(myrows[r * 128 + v]);
                #pragma unroll
                for (int t = 0; t < 6; t++) fma2(acc[r][t], wp[t], s2);
            }
        }

        #pragma unroll
        for (int r = 0; r < R; r++) {
            float4* dst = (float4*)(g_mixed + (size_t)(r0 + r) * 384);
            #pragma unroll
            for (int i = 0; i < 3; i++) {
                float2 a = f2unpack(acc[r][2 * i]);
                float2 b = f2unpack(acc[r][2 * i + 1]);
                float4 o; o.x = a.x; o.y = a.y; o.z = b.x; o.w = b.y;
                dst[lane + 32 * i] = o;
            }
        }
        __syncwarp();
    }
}

// ---------------------------------------------------------------------------
// tf32 mma.sync fused kernel for one depth-D path.
// Tile = 16 batch rows; GEMM: tmp[u, n=t*D+k] = sum_v W[u,v]*x2[b0+t,in2s+v*D+k]
//   M=128(u) x K=128(v) x N=16*D(n).  Warps: 4 over m (32 rows), 2 over n.
// Accums dumped to smem [n][u]; epilogue thread owns u=tid&127, t-half=tid>>7:
//   out[b,outs0+u]     = (sum_k x1[b,u*D+k]*tmp[u,tD+k]) * inv_d * mask
//   out[b,outs1+u*D+k] = x1[b,u*D+k] * g_mixed[b,moff+u] * mask     (HAS_M1)
// ---------------------------------------------------------------------------
template<int D, bool HAS_M1>
__global__ void __launch_bounds__(256, 1)
tc_group(const float* __restrict__ x1, const float* __restrict__ x2,
         const float* __restrict__ weight, const float* __restrict__ mask,
         float* __restrict__ out,
         int in1s, int in2s, int outs0, int outs1, int ws0, int moff,
         float inv_d)
{
    constexpr int T   = 16;
    constexpr int N   = T * D;        // 16 / 48 / 80 / 112
    constexpr int NT2 = N / 16;       // n8-tiles per warp (each warp owns N/2)
    constexpr int PW  = 132;          // Ws/Bs pitch (words)
    constexpr int PT  = 130;          // Ts pitch (words)

    extern __shared__ float sm[];
    float* Ws = sm;                   // [128][PW] tf32 words
    float* Bs = sm + 128 * PW;        // [N][PW]   tf32 words
    float* Ts = Bs + N * PW;          // [N][PT]   fp32 accums

    const int tid  = threadIdx.x;
    const int lane = tid & 31;
    const int warp = tid >> 5;
    const int gid  = lane >> 2;       // 0..7
    const int tig  = lane & 3;        // 0..3
    const int wm   = warp & 3;        // m-block (32 u rows)
    const int wn   = warp >> 2;       // n-half
    const int nh   = wn * (N / 2);

    uint32_t* Wu = (uint32_t*)Ws;
    uint32_t* Bu = (uint32_t*)Bs;

    // Build A = W (tf32), pitch-132 (conflict-free frag reads). Once.
    for (int f = tid; f < 128 * 32; f += 256) {
        int u = f >> 5, q = f & 31;
        float4 w4 = ((const float4*)(weight + ws0))[f];
        Wu[u * PW + 4 * q + 0] = cvt_tf32(w4.x);
        Wu[u * PW + 4 * q + 1] = cvt_tf32(w4.y);
        Wu[u * PW + 4 * q + 2] = cvt_tf32(w4.z);
        Wu[u * PW + 4 * q + 3] = cvt_tf32(w4.w);
    }

    // Hoisted per-thread epilogue constants (u fixed per thread).
    const int eu = tid & 127;
    const int th = tid >> 7;
    const float mk0 = mask[outs0 + eu];
    float mkx[D];
    if (HAS_M1) {
        #pragma unroll
        for (int k = 0; k < D; k++) mkx[k] = mask[outs1 + eu * D + k];
    }
    __syncthreads();

    for (int tile = blockIdx.x; tile < NB / T; tile += gridDim.x) {
        const int b0 = tile * T;

        // ---- build B tile: Bs[n=t*D+k][v] = tf32(x2[b0+t, in2s + v*D + k]) ----
        for (int f = tid; f < T * 32 * D; f += 256) {
            int t = f / (32 * D), q = f - t * (32 * D);
            float4 v4 = ((const float4*)(x2 + (size_t)(b0 + t) * IN_DIM + in2s))[q];
            float c[4] = {v4.x, v4.y, v4.z, v4.w};
            int e = 4 * q;
            #pragma unroll
            for (int j = 0; j < 4; j++) {
                int v = (e + j) / D, k = (e + j) % D;
                Bu[(t * D + k) * PW + v] = cvt_tf32(c[j]);
            }
        }
        __syncthreads();

        // ---- MMA: 16 K-steps of k=8 over v ----
        float acc[2][NT2][4];
        #pragma unroll
        for (int mt = 0; mt < 2; mt++)
            #pragma unroll
            for (int nt = 0; nt < NT2; nt++)
                #pragma unroll
                for (int j = 0; j < 4; j++) acc[mt][nt][j] = 0.0f;

        #pragma unroll
        for (int s = 0; s < 16; s++) {
            const int v0 = 8 * s;
            uint32_t a[2][4];
            #pragma unroll
            for (int mt = 0; mt < 2; mt++) {
                int u0 = wm * 32 + mt * 16;
                a[mt][0] = Wu[(u0 + gid    ) * PW + v0 + tig    ];
                a[mt][1] = Wu[(u0 + gid + 8) * PW + v0 + tig    ];
                a[mt][2] = Wu[(u0 + gid    ) * PW + v0 + tig + 4];
                a[mt][3] = Wu[(u0 + gid + 8) * PW + v0 + tig + 4];
            }
            #pragma unroll
            for (int nt = 0; nt < NT2; nt++) {
                int n0 = nh + nt * 8;
                uint32_t br0 = Bu[(n0 + gid) * PW + v0 + tig    ];
                uint32_t br1 = Bu[(n0 + gid) * PW + v0 + tig + 4];
                mma_tf32(acc[0][nt], a[0], br0, br1);
                mma_tf32(acc[1][nt], a[1], br0, br1);
            }
        }

        // ---- dump accums to Ts[n][u] ----
        #pragma unroll
        for (int mt = 0; mt < 2; mt++) {
            int ub = wm * 32 + mt * 16 + gid;
            #pragma unroll
            for (int nt = 0; nt < NT2; nt++) {
                int n0 = nh + nt * 8 + 2 * tig;
                Ts[(n0    ) * PT + ub    ] = acc[mt][nt][0];
                Ts[(n0 + 1) * PT + ub    ] = acc[mt][nt][1];
                Ts[(n0    ) * PT + ub + 8] = acc[mt][nt][2];
                Ts[(n0 + 1) * PT + ub + 8] = acc[mt][nt][3];
            }
        }
        __syncthreads();

        // ---- fused epilogue: thread owns u=eu, handles 8 t values ----
        #pragma unroll
        for (int tt = 0; tt < 8; tt++) {
            const int t = th * 8 + tt;
            const size_t b = (size_t)(b0 + t);
            const float* xr = x1 + b * IN_DIM + in1s + eu * D;
            float xv[D];
            #pragma unroll
            for (int k = 0; k < D; k++) xv[k] = __ldg(xr + k);

            float accv = 0.0f;
            #pragma unroll
            for (int k = 0; k < D; k++)
                accv = fmaf(xv[k], Ts[(t * D + k) * PT + eu], accv);
            out[b * OUT_DIM + outs0 + eu] = accv * inv_d * mk0;

            if (HAS_M1) {
                float mix = g_mixed[b * 384 + moff + eu];
                float* orow = out + b * OUT_DIM + outs1 + eu * D;
                #pragma unroll
                for (int k = 0; k < D; k++)
                    orow[k] = xv[k] * mix * mkx[k];
            }
        }
        // no sync needed: next Bs build is disjoint from Ts reads; the
        // post-build __syncthreads() orders epilogue(i) vs dump(i+1).
    }
}

// ---------------------------------------------------------------------------
extern "C" void kernel_launch(void* const* d_in, const int* in_sizes, int n_in,
                              void* d_out, int out_size)
{
    (void)in_sizes; (void)n_in; (void)out_size;
    const float* x1   = (const float*)d_in[0];
    const float* x2   = (const float*)d_in[1];
    const float* w    = (const float*)d_in[2];
    const float* mask = (const float*)d_in[3];
    float* out        = (float*)d_out;

    const int SM_M1 = (128 * 384 + 8 * 4 * 128) * 4;                  // 212992
    const int SM_T1 = (128 * 132 + 16  * 132 + 16  * 130) * 4;        //  84352
    const int SM_T3 = (128 * 132 + 48  * 132 + 48  * 130) * 4;        // 117888
    const int SM_T5 = (128 * 132 + 80  * 132 + 80  * 130) * 4;        // 151424
    const int SM_T7 = (128 * 132 + 112 * 132 + 112 * 130) * 4;        // 184960

    cudaFuncSetAttribute(mode1_kernel,
                         cudaFuncAttributeMaxDynamicSharedMemorySize, SM_M1);
    cudaFuncSetAttribute(tc_group<1, false>,
                         cudaFuncAttributeMaxDynamicSharedMemorySize, SM_T1);
    cudaFuncSetAttribute(tc_group<3, true>,
                         cudaFuncAttributeMaxDynamicSharedMemorySize, SM_T3);
    cudaFuncSetAttribute(tc_group<5, true>,
                         cudaFuncAttributeMaxDynamicSharedMemorySize, SM_T5);
    cudaFuncSetAttribute(tc_group<7, true>,
                         cudaFuncAttributeMaxDynamicSharedMemorySize, SM_T7);

    const int GRID = 148;

    // mode-1 first (paths 3/5/7 consume g_mixed; same-stream ordering).
    mode1_kernel<<<GRID, 256, SM_M1>>>(x2, w);

    tc_group<1, false><<<GRID, 256, SM_T1>>>(
        x1, x2, w, mask, out, 0, 0, 0, 0, 0 * 16384, 0, 1.0f);
    tc_group<3, true><<<GRID, 256, SM_T3>>>(
        x1, x2, w, mask, out, 128, 128, 128, 512, 1 * 16384, 0, C_INV3);
    tc_group<5, true><<<GRID, 256, SM_T5>>>(
        x1, x2, w, mask, out, 512, 512, 256, 896, 2 * 16384, 128, C_INV5);
    tc_group<7, true><<<GRID, 256, SM_T7>>>(
        x1, x2, w, mask, out, 1152, 1152, 384, 1536, 3 * 16384, 256, C_INV7);
}

// round 7
// speedup vs baseline: 2.4548x; 1.9054x over previous
#include <cuda_runtime.h>
#include <cstdint>

#define NB      32768
#define IN_DIM  2048
#define OUT_DIM 2432

#define C_INV3 0.57735026918962576451f
#define C_INV5 0.44721359549995793928f
#define C_INV7 0.37796447300922722721f

// Scratch for mode-1 mixed factors: [NB][384], pre-scaled by 1/sqrt(d).
__device__ float g_mixed[(size_t)NB * 384];

// ---------------- tf32 mma.sync helpers (base sm_103) ----------------
__device__ __forceinline__ uint32_t cvt_tf32(float x) {
    uint32_t r; asm("cvt.rna.tf32.f32 %0, %1;" : "=r"(r) : "f"(x)); return r;
}
__device__ __forceinline__ void mma_tf32(float c[4], const uint32_t a[4],
                                         uint32_t b0, uint32_t b1) {
    asm volatile(
        "mma.sync.aligned.m16n8k8.row.col.f32.tf32.tf32.f32 "
        "{%0,%1,%2,%3}, {%4,%5,%6,%7}, {%8,%9}, {%0,%1,%2,%3};"
        : "+f"(c[0]), "+f"(c[1]), "+f"(c[2]), "+f"(c[3])
        : "r"(a[0]), "r"(a[1]), "r"(a[2]), "r"(a[3]), "r"(b0), "r"(b1));
}
__device__ __forceinline__ void bar_g(int id) {
    asm volatile("bar.sync %0, 128;" :: "r"(id) : "memory");
}

// ---------------------------------------------------------------------------
// mode-1 GEMM: g_mixed[b, u'] = sum_v x2[b,v] * W'[u',v] * scale(u')
//   A = x2 tile [16 t][128 v] (row-major, pitch 132)
//   B = stacked scaled W' [384 u'][128 v], XOR-swizzled, no pad (196KB smem)
//   8 warps each own 48 n-cols (6 n8-tiles).
// ---------------------------------------------------------------------------
__global__ void __launch_bounds__(256, 1)
mode1_mma(const float* __restrict__ x2, const float* __restrict__ weight)
{
    extern __shared__ float sm[];
    uint32_t* Wb  = (uint32_t*)sm;          // [384][128] swizzled
    float*    x2s = sm + 384 * 128;         // [16][132]
    uint32_t* x2u = (uint32_t*)x2s;

    const int tid  = threadIdx.x;
    const int lane = tid & 31;
    const int warp = tid >> 5;
    const int gid  = lane >> 2;
    const int tig  = lane & 3;

    // Build W' (scaled, tf32, swizzled). Once.
    for (int f = tid; f < 384 * 32; f += 256) {
        int u = f >> 5, q = f & 31;
        int p = u >> 7;
        float sc = (p == 0) ? C_INV3 : ((p == 1) ? C_INV5 : C_INV7);
        float4 w4 = ((const float4*)(weight + 4 * 16384))[f];
        float c[4] = {w4.x * sc, w4.y * sc, w4.z * sc, w4.w * sc};
        int sw = (u & 7) << 2;
        #pragma unroll
        for (int j = 0; j < 4; j++)
            Wb[u * 128 + ((4 * q + j) ^ sw)] = cvt_tf32(c[j]);
    }
    __syncthreads();

    const int n_base = warp * 48;

    for (int s = blockIdx.x; s < NB / 16; s += gridDim.x) {
        const int b0 = s * 16;
        // Build A tile (tf32), vectorized STS.
        for (int f = tid; f < 16 * 32; f += 256) {
            int t = f >> 5, q = f & 31;
            float4 v4 = ((const float4*)(x2 + (size_t)(b0 + t) * IN_DIM))[q];
            uint4 o;
            o.x = cvt_tf32(v4.x); o.y = cvt_tf32(v4.y);
            o.z = cvt_tf32(v4.z); o.w = cvt_tf32(v4.w);
            *(uint4*)(x2u + t * 132 + 4 * q) = o;
        }
        __syncthreads();

        float acc[6][4];
        #pragma unroll
        for (int nt = 0; nt < 6; nt++)
            #pragma unroll
            for (int j = 0; j < 4; j++) acc[nt][j] = 0.0f;

        #pragma unroll
        for (int s16 = 0; s16 < 16; s16++) {
            const int v0 = 8 * s16;
            uint32_t a[4];
            a[0] = x2u[(gid    ) * 132 + v0 + tig    ];
            a[1] = x2u[(gid + 8) * 132 + v0 + tig    ];
            a[2] = x2u[(gid    ) * 132 + v0 + tig + 4];
            a[3] = x2u[(gid + 8) * 132 + v0 + tig + 4];
            #pragma unroll
            for (int nt = 0; nt < 6; nt++) {
                int ur = n_base + nt * 8 + gid;
                int sw = (ur & 7) << 2;
                uint32_t b0r = Wb[ur * 128 + ((v0 + tig    ) ^ sw)];
                uint32_t b1r = Wb[ur * 128 + ((v0 + tig + 4) ^ sw)];
                mma_tf32(acc[nt], a, b0r, b1r);
            }
        }

        // Dump straight to gmem: c0,c1 -> row b0+gid; c2,c3 -> row b0+gid+8.
        #pragma unroll
        for (int nt = 0; nt < 6; nt++) {
            int n0 = n_base + nt * 8 + 2 * tig;
            float2 lo; lo.x = acc[nt][0]; lo.y = acc[nt][1];
            float2 hi; hi.x = acc[nt][2]; hi.y = acc[nt][3];
            *(float2*)(g_mixed + (size_t)(b0 + gid    ) * 384 + n0) = lo;
            *(float2*)(g_mixed + (size_t)(b0 + gid + 8) * 384 + n0) = hi;
        }
        __syncthreads();   // A-tile reads done before next build
    }
}

// ---------------------------------------------------------------------------
// tc_group: 512 threads = 4 independent 128-thread pipelines (named barriers).
// Group g processes 8-row subtiles; GEMM M=128(u) x K=128(v) x N=8D(n=t*D+k):
//   tmp[u,n] = sum_v W[u,v] * x2[b0+t, in2s+v*D+k]
// B tile and accumulator dump share one [8D][132] buffer (aliased).
// Epilogue: lane owns u-quad 4*lane -> fully vectorized loads/stores.
// ---------------------------------------------------------------------------
template<int D, bool HAS_M1>
__global__ void __launch_bounds__(512, 1)
tc_group(const float* __restrict__ x1, const float* __restrict__ x2,
         const float* __restrict__ weight, const float* __restrict__ mask,
         float* __restrict__ out,
         int in1s, int in2s, int outs0, int outs1, int ws0, int moff,
         float inv_d)
{
    constexpr int N  = 8 * D;
    constexpr int PW = 132;

    extern __shared__ float sm[];
    uint32_t* Wu = (uint32_t*)sm;                       // [128][PW]

    const int tid  = threadIdx.x;
    const int g    = tid >> 7;                          // group 0..3
    const int gt   = tid & 127;
    const int lane = tid & 31;
    const int wg   = (tid >> 5) & 3;                    // m-warp in group
    const int gid  = lane >> 2;
    const int tig  = lane & 3;
    const int bar  = g + 1;

    float*    BT  = sm + 128 * PW + g * (N * PW);       // aliased B/Ts buffer
    uint32_t* BTu = (uint32_t*)BT;

    // Build Ws (tf32, pitch 132). Once, all 512 threads.
    for (int f = tid; f < 128 * 32; f += 512) {
        int u = f >> 5, q = f & 31;
        float4 w4 = ((const float4*)(weight + ws0))[f];
        uint4 o;
        o.x = cvt_tf32(w4.x); o.y = cvt_tf32(w4.y);
        o.z = cvt_tf32(w4.z); o.w = cvt_tf32(w4.w);
        *(uint4*)(Wu + u * PW + 4 * q) = o;
    }
    __syncthreads();

    for (int s = blockIdx.x * 4 + g; s < NB / 8; s += gridDim.x * 4) {
        const int b0 = s * 8;

        // ---- build B: BT[t*D+k][v] = tf32(x2[b0+t, in2s + v*D + k]) ----
        for (int f = gt; f < 256 * D; f += 128) {
            int t = f / (32 * D);
            int q = f - t * (32 * D);
            float4 v4 = ((const float4*)(x2 + (size_t)(b0 + t) * IN_DIM + in2s))[q];
            float c[4] = {v4.x, v4.y, v4.z, v4.w};
            int e = 4 * q;
            #pragma unroll
            for (int j = 0; j < 4; j++) {
                int v = (e + j) / D, k = (e + j) % D;
                BTu[(t * D + k) * PW + v] = cvt_tf32(c[j]);
            }
        }
        bar_g(bar);

        // ---- MMA: 16 K-steps of k=8 ----
        float acc[2][D][4];
        #pragma unroll
        for (int mt = 0; mt < 2; mt++)
            #pragma unroll
            for (int nt = 0; nt < D; nt++)
                #pragma unroll
                for (int j = 0; j < 4; j++) acc[mt][nt][j] = 0.0f;

        #pragma unroll
        for (int s16 = 0; s16 < 16; s16++) {
            const int v0 = 8 * s16;
            uint32_t a[2][4];
            #pragma unroll
            for (int mt = 0; mt < 2; mt++) {
                int u0 = wg * 32 + mt * 16;
                a[mt][0] = Wu[(u0 + gid    ) * PW + v0 + tig    ];
                a[mt][1] = Wu[(u0 + gid + 8) * PW + v0 + tig    ];
                a[mt][2] = Wu[(u0 + gid    ) * PW + v0 + tig + 4];
                a[mt][3] = Wu[(u0 + gid + 8) * PW + v0 + tig + 4];
            }
            #pragma unroll
            for (int nt = 0; nt < D; nt++) {
                uint32_t b0r = BTu[(nt * 8 + gid) * PW + v0 + tig    ];
                uint32_t b1r = BTu[(nt * 8 + gid) * PW + v0 + tig + 4];
                mma_tf32(acc[0][nt], a[0], b0r, b1r);
                mma_tf32(acc[1][nt], a[1], b0r, b1r);
            }
        }
        bar_g(bar);          // all 4 warps done reading B

        // ---- dump accums into the same buffer as Ts[n][u] ----
        #pragma unroll
        for (int mt = 0; mt < 2; mt++) {
            int ub = wg * 32 + mt * 16 + gid;
            #pragma unroll
            for (int nt = 0; nt < D; nt++) {
                int n0 = nt * 8 + 2 * tig;
                BT[(n0    ) * PW + ub    ] = acc[mt][nt][0];
                BT[(n0 + 1) * PW + ub    ] = acc[mt][nt][1];
                BT[(n0    ) * PW + ub + 8] = acc[mt][nt][2];
                BT[(n0 + 1) * PW + ub + 8] = acc[mt][nt][3];
            }
        }
        bar_g(bar);

        // ---- vectorized epilogue: warp wg handles t = p*4+wg, lane owns 4u ----
        #pragma unroll
        for (int p = 0; p < 2; p++) {
            const int t = p * 4 + wg;
            const size_t b = (size_t)(b0 + t);

            float xv[4 * D];       // xv[uj*D + k]
            float tv[4 * D];       // tv[k*4 + uj]
            const float4* x1p =
                (const float4*)(x1 + b * IN_DIM + in1s + (size_t)4 * lane * D);
            #pragma unroll
            for (int q = 0; q < D; q++) {
                float4 t4 = __ldg(x1p + q);
                xv[4 * q + 0] = t4.x; xv[4 * q + 1] = t4.y;
                xv[4 * q + 2] = t4.z; xv[4 * q + 3] = t4.w;
            }
            #pragma unroll
            for (int k = 0; k < D; k++) {
                float4 t4 = *(const float4*)(BT + (t * D + k) * PW + 4 * lane);
                tv[4 * k + 0] = t4.x; tv[4 * k + 1] = t4.y;
                tv[4 * k + 2] = t4.z; tv[4 * k + 3] = t4.w;
            }

            float m4[4] = {0.0f, 0.0f, 0.0f, 0.0f};
            #pragma unroll
            for (int uj = 0; uj < 4; uj++)
                #pragma unroll
                for (int k = 0; k < D; k++)
                    m4[uj] = fmaf(xv[uj * D + k], tv[4 * k + uj], m4[uj]);

            {
                float4 mk = __ldg((const float4*)(mask + outs0) + lane);
                float4 o;
                o.x = m4[0] * inv_d * mk.x; o.y = m4[1] * inv_d * mk.y;
                o.z = m4[2] * inv_d * mk.z; o.w = m4[3] * inv_d * mk.w;
                *(float4*)(out + b * OUT_DIM + outs0 + 4 * lane) = o;
            }

            if (HAS_M1) {
                float4 mx = __ldg((const float4*)(g_mixed + b * 384 + moff) + lane);
                float mix[4] = {mx.x, mx.y, mx.z, mx.w};
                const float4* mk1 =
                    (const float4*)(mask + outs1 + (size_t)4 * lane * D);
                float4* op = (float4*)(out + b * OUT_DIM + outs1 + (size_t)4 * lane * D);
                #pragma unroll
                for (int q = 0; q < D; q++) {
                    float4 mq = __ldg(mk1 + q);
                    float4 o;
                    o.x = xv[4 * q + 0] * mix[(4 * q + 0) / D] * mq.x;
                    o.y = xv[4 * q + 1] * mix[(4 * q + 1) / D] * mq.y;
                    o.z = xv[4 * q + 2] * mix[(4 * q + 2) / D] * mq.z;
                    o.w = xv[4 * q + 3] * mix[(4 * q + 3) / D] * mq.w;
                    op[q] = o;
                }
            }
        }
        bar_g(bar);          // Ts reads done before next build overwrites
    }
}

// ---------------------------------------------------------------------------
extern "C" void kernel_launch(void* const* d_in, const int* in_sizes, int n_in,
                              void* d_out, int out_size)
{
    (void)in_sizes; (void)n_in; (void)out_size;
    const float* x1   = (const float*)d_in[0];
    const float* x2   = (const float*)d_in[1];
    const float* w    = (const float*)d_in[2];
    const float* mask = (const float*)d_in[3];
    float* out        = (float*)d_out;

    const int SM_M1 = (384 * 128 + 16 * 132) * 4;                 // 205056
    const int SM_T1 = (128 * 132 + 4 * 8  * 1 * 132) * 4;         //  84480
    const int SM_T3 = (128 * 132 + 4 * 8  * 3 * 132) * 4;         // 118272
    const int SM_T5 = (128 * 132 + 4 * 8  * 5 * 132) * 4;         // 152064
    const int SM_T7 = (128 * 132 + 4 * 8  * 7 * 132) * 4;         // 185856

    cudaFuncSetAttribute(mode1_mma,
                         cudaFuncAttributeMaxDynamicSharedMemorySize, SM_M1);
    cudaFuncSetAttribute(tc_group<1, false>,
                         cudaFuncAttributeMaxDynamicSharedMemorySize, SM_T1);
    cudaFuncSetAttribute(tc_group<3, true>,
                         cudaFuncAttributeMaxDynamicSharedMemorySize, SM_T3);
    cudaFuncSetAttribute(tc_group<5, true>,
                         cudaFuncAttributeMaxDynamicSharedMemorySize, SM_T5);
    cudaFuncSetAttribute(tc_group<7, true>,
                         cudaFuncAttributeMaxDynamicSharedMemorySize, SM_T7);

    const int GRID = 148;

    // mode-1 first (paths 3/5/7 consume g_mixed; same-stream ordering).
    mode1_mma<<<GRID, 256, SM_M1>>>(x2, w);

    tc_group<1, false><<<GRID, 512, SM_T1>>>(
        x1, x2, w, mask, out, 0, 0, 0, 0, 0 * 16384, 0, 1.0f);
    tc_group<3, true><<<GRID, 512, SM_T3>>>(
        x1, x2, w, mask, out, 128, 128, 128, 512, 1 * 16384, 0, C_INV3);
    tc_group<5, true><<<GRID, 512, SM_T5>>>(
        x1, x2, w, mask, out, 512, 512, 256, 896, 2 * 16384, 128, C_INV5);
    tc_group<7, true><<<GRID, 512, SM_T7>>>(
        x1, x2, w, mask, out, 1152, 1152, 384, 1536, 3 * 16384, 256, C_INV7);
}